// round 10
// baseline (speedup 1.0000x reference)
#include <cuda_runtime.h>

#define BATCH 2048
#define NPTS  4095
#define TPB   512
#define CH    1024          // elements per pass
#define LEPT  2             // TPB*LEPT = CH
#define NPASS 4
#define NWARP (TPB/32)      // 16

__device__ float g_partial[BATCH];
__device__ int   g_count = 0;

// 3 rotating buffers × 3 components × 1024 floats = 36 KB
#define SMEM_BYTES (3 * 3 * CH * 4)

extern __shared__ __align__(16) float sstage[];

__device__ __forceinline__ void phaseA(int p, float* __restrict__ bx,
                                       float* __restrict__ by,
                                       float* __restrict__ bz,
                                       const float* __restrict__ s3b,
                                       const float* __restrict__ s2b,
                                       const float* __restrict__ dfb,
                                       int t)
{
    #pragma unroll
    for (int k = 0; k < LEPT; k++) {
        const int i = t + k * TPB;          // 0..1023, coalesced
        const int g = i + p * CH;
        float vx = 0.f, vy = 0.f, vz = 0.f;
        if (g < NPTS) {                      // only g==4095 (p==3) fails
            float r3  = s3b[g];
            float th3 = s3b[g + NPTS];
            float ph3 = s3b[g + 2 * NPTS];
            float r2  = s2b[g];
            float th2 = s2b[g + NPTS];
            float ph2 = s2b[g + 2 * NPTS];
            float dt  = dfb[g];
            float dp  = dfb[g + NPTS];

            float st, ct, sp, cp;
            __sincosf(th3 + dt, &st, &ct);
            __sincosf(ph3 + dp, &sp, &cp);
            float rst = r3 * st;
            vx = rst * cp; vy = rst * sp; vz = r3 * ct;
            __sincosf(th2, &st, &ct);
            __sincosf(ph2, &sp, &cp);
            rst = r2 * st;
            vx -= rst * cp; vy -= rst * sp; vz -= r2 * ct;
        }
        bx[i] = vx; by[i] = vy; bz[i] = vz;
    }
}

__global__ void __launch_bounds__(TPB, 3)
mpd_fused_kernel(const float* __restrict__ o3,
                 const float* __restrict__ s3,
                 const float* __restrict__ o2,
                 const float* __restrict__ s2,
                 const float* __restrict__ df,
                 float* __restrict__ out)
{
    __shared__ float wt[NPASS][3][NWARP];
    __shared__ float red[NWARP];
    __shared__ int   is_last;

    const int b = blockIdx.x;
    const int t = threadIdx.x;
    const unsigned lane = t & 31u;
    const unsigned warp = t >> 5;

    const float* __restrict__ s3b = s3 + (size_t)b * (3 * NPTS);
    const float* __restrict__ s2b = s2 + (size_t)b * (3 * NPTS);
    const float* __restrict__ dfb = df + (size_t)b * (2 * NPTS);

    // prologue: fill buffer 0 with pass 0
    phaseA(0, sstage, sstage + CH, sstage + 2 * CH, s3b, s2b, dfb, t);
    __syncthreads();

    const float dx = o3[b * 3 + 0] - o2[b * 3 + 0];
    const float dy = o3[b * 3 + 1] - o2[b * 3 + 1];
    const float dz = o3[b * 3 + 2] - o2[b * 3 + 2];
    float offx = dx, offy = dy, offz = dz;
    float acc = 0.f;
    if (t == 0) acc = fabsf(dx) + fabsf(dy) + fabsf(dz);   // j=0 (origin)

    const int base = LEPT * t;               // float2 slot

    #pragma unroll
    for (int p = 0; p < NPASS; p++) {
        float* cbx = sstage + ((p % 3) * 3 + 0) * CH;
        float* cby = sstage + ((p % 3) * 3 + 1) * CH;
        float* cbz = sstage + ((p % 3) * 3 + 2) * CH;

        // issue next pass's load burst FIRST (keeps DRAM busy through B)
        if (p + 1 < NPASS) {
            float* nbx = sstage + (((p + 1) % 3) * 3 + 0) * CH;
            float* nby = sstage + (((p + 1) % 3) * 3 + 1) * CH;
            float* nbz = sstage + (((p + 1) % 3) * 3 + 2) * CH;
            phaseA(p + 1, nbx, nby, nbz, s3b, s2b, dfb, t);
        }

        // ---- B_a: thread totals + warp scan ----
        float2 X = *reinterpret_cast<const float2*>(cbx + base);
        float2 Y = *reinterpret_cast<const float2*>(cby + base);
        float2 Z = *reinterpret_cast<const float2*>(cbz + base);
        const float tx = X.x + X.y;
        const float ty = Y.x + Y.y;
        const float tz = Z.x + Z.y;

        float ix = tx, iy = ty, iz = tz;
        #pragma unroll
        for (int o = 1; o < 32; o <<= 1) {
            float ax = __shfl_up_sync(0xFFFFFFFFu, ix, o);
            float ay = __shfl_up_sync(0xFFFFFFFFu, iy, o);
            float az = __shfl_up_sync(0xFFFFFFFFu, iz, o);
            if (lane >= (unsigned)o) { ix += ax; iy += ay; iz += az; }
        }
        if (lane == 31) {
            wt[p][0][warp] = ix; wt[p][1][warp] = iy; wt[p][2][warp] = iz;
        }
        __syncthreads();      // fences wt[p]; also the buffer-rotation fence

        // ---- B_b: redundant warp-total scan + abs sweep ----
        float px = (lane < NWARP) ? wt[p][0][lane] : 0.f;
        float py = (lane < NWARP) ? wt[p][1][lane] : 0.f;
        float pz = (lane < NWARP) ? wt[p][2][lane] : 0.f;
        #pragma unroll
        for (int o = 1; o < NWARP; o <<= 1) {
            float ax = __shfl_up_sync(0xFFFFFFFFu, px, o);
            float ay = __shfl_up_sync(0xFFFFFFFFu, py, o);
            float az = __shfl_up_sync(0xFFFFFFFFu, pz, o);
            if (lane >= (unsigned)o) { px += ax; py += ay; pz += az; }
        }
        const unsigned src = (warp == 0) ? 0u : (warp - 1u);
        float wpx = __shfl_sync(0xFFFFFFFFu, px, src);
        float wpy = __shfl_sync(0xFFFFFFFFu, py, src);
        float wpz = __shfl_sync(0xFFFFFFFFu, pz, src);

        float ox = offx + (ix - tx) + ((warp == 0) ? 0.f : wpx);
        float oy = offy + (iy - ty) + ((warp == 0) ? 0.f : wpy);
        float oz = offz + (iz - tz) + ((warp == 0) ? 0.f : wpz);

        const int gbase = p * CH + base;
        ox += X.x; oy += Y.x; oz += Z.x;
        if (gbase < NPTS)
            acc += fabsf(ox) + fabsf(oy) + fabsf(oz);
        ox += X.y; oy += Y.y; oz += Z.y;
        if (gbase + 1 < NPTS)
            acc += fabsf(ox) + fabsf(oy) + fabsf(oz);

        // advance running offset by this pass's block total
        offx += __shfl_sync(0xFFFFFFFFu, px, NWARP - 1);
        offy += __shfl_sync(0xFFFFFFFFu, py, NWARP - 1);
        offz += __shfl_sync(0xFFFFFFFFu, pz, NWARP - 1);
    }

    // ---- block reduce ----
    #pragma unroll
    for (int o = 16; o > 0; o >>= 1)
        acc += __shfl_down_sync(0xFFFFFFFFu, acc, o);
    if (lane == 0) red[warp] = acc;
    __syncthreads();
    if (warp == 0) {
        float a = (lane < NWARP) ? red[lane] : 0.f;
        #pragma unroll
        for (int o = 16; o > 0; o >>= 1)
            a += __shfl_down_sync(0xFFFFFFFFu, a, o);
        if (lane == 0) g_partial[b] = a * (1.0f / (NPTS + 1));
    }

    // ---- fused deterministic final reduction ----
    if (t == 0) {
        __threadfence();
        int ticket = atomicAdd(&g_count, 1);
        is_last = (ticket == (int)gridDim.x - 1) ? 1 : 0;
    }
    __syncthreads();
    if (is_last) {
        float a = __ldcg(&g_partial[t])
                + __ldcg(&g_partial[t + TPB])
                + __ldcg(&g_partial[t + 2 * TPB])
                + __ldcg(&g_partial[t + 3 * TPB]);
        #pragma unroll
        for (int o = 16; o > 0; o >>= 1)
            a += __shfl_down_sync(0xFFFFFFFFu, a, o);
        if (lane == 0) red[warp] = a;
        __syncthreads();
        if (warp == 0) {
            float v = (lane < NWARP) ? red[lane] : 0.f;
            #pragma unroll
            for (int o = 16; o > 0; o >>= 1)
                v += __shfl_down_sync(0xFFFFFFFFu, v, o);
            if (lane == 0) {
                out[0] = v;
                atomicExch(&g_count, 0);   // reset for next graph replay
            }
        }
    }
}

extern "C" void kernel_launch(void* const* d_in, const int* in_sizes, int n_in,
                              void* d_out, int out_size)
{
    const float* o3 = (const float*)d_in[0];  // origin_3D        (B,3,1)
    const float* s3 = (const float*)d_in[1];  // spherical_3D     (B,3,N)
    const float* o2 = (const float*)d_in[2];  // origin_2D        (B,3,1)
    const float* s2 = (const float*)d_in[3];  // spherical_2D     (B,3,N)
    const float* df = (const float*)d_in[4];  // deformation_field(B,2,N)
    float* out = (float*)d_out;

    cudaFuncSetAttribute(mpd_fused_kernel,
                         cudaFuncAttributeMaxDynamicSharedMemorySize, SMEM_BYTES);
    mpd_fused_kernel<<<BATCH, TPB, SMEM_BYTES>>>(o3, s3, o2, s2, df, out);
}